// round 7
// baseline (speedup 1.0000x reference)
#include <cuda_runtime.h>
#include <cuda_bf16.h>
#include <math.h>

// ---------------------------------------------------------------------------
#define BB 512
#define VV 6890
#define NJ 24
#define NBETA 10
#define NP 207
#define NJO 19
#define VC (VV*3)              // 20670
#define KTOT 217
#define KPAD 224               // 7*32
#define JNT_OFF  (BB*VC)
#define ROT_OFF  (JNT_OFF + BB*NJO*3)

typedef unsigned long long u64;

__device__ __forceinline__ u64 ffma2(u64 a, u64 b, u64 c) {
    u64 d;
    asm("fma.rn.f32x2 %0, %1, %2, %3;" : "=l"(d) : "l"(a), "l"(b), "l"(c));
    return d;
}
__device__ __forceinline__ u64 pack2(float lo, float hi) {
    u64 d;
    asm("mov.b64 %0, {%1, %2};" : "=l"(d) : "f"(lo), "f"(hi));
    return d;
}
__device__ __forceinline__ float2 unpack2(u64 v) {
    float2 f;
    asm("mov.b64 {%0, %1}, %2;" : "=f"(f.x), "=f"(f.y) : "l"(v));
    return f;
}
__device__ __forceinline__ void cp_async8(unsigned saddr, const void* gaddr, int srcsize) {
    asm volatile("cp.async.ca.shared.global [%0], [%1], 8, %2;"
                 :: "r"(saddr), "l"(gaddr), "r"(srcsize));
}
__device__ __forceinline__ void cp_async16(unsigned saddr, const void* gaddr) {
    asm volatile("cp.async.ca.shared.global [%0], [%1], 16;"
                 :: "r"(saddr), "l"(gaddr));
}
__device__ __forceinline__ void cp_commit() {
    asm volatile("cp.async.commit_group;");
}
template<int N>
__device__ __forceinline__ void cp_wait() {
    asm volatile("cp.async.wait_group %0;" :: "n"(N));
}

// ---------------------------------------------------------------------------
__device__ float g_pfT[KPAD * BB];        // pose-feature+beta, [k][b]
__device__ float g_A[BB * NJ * 12];       // A' 3x4 per (b,j)
__device__ float g_jmp[NJ * 8 * 33];
__device__ float g_jm[NJ * 33];
__device__ float g_jpart[BB * 14 * 57];

// ---------------------------------------------------------------------------
// Kernel 0: batch-independent precompute for rest joints
// ---------------------------------------------------------------------------
__global__ void __launch_bounds__(128) k_jm(const float* __restrict__ vt,
                                            const float* __restrict__ shp,
                                            const float* __restrict__ sr)
{
    int j = blockIdx.x, part = blockIdx.y;
    int vs = part * 862;
    int ve = vs + 862; if (ve > VV) ve = VV;

    float acc[33];
    #pragma unroll
    for (int i = 0; i < 33; ++i) acc[i] = 0.f;

    for (int v = vs + threadIdx.x; v < ve; v += 128) {
        float w = sr[v * NJ + j];
        acc[0] += vt[v*3+0] * w;
        acc[1] += vt[v*3+1] * w;
        acc[2] += vt[v*3+2] * w;
        #pragma unroll
        for (int k = 0; k < NBETA; ++k) {
            const float* s = shp + k * VC + v * 3;
            acc[3+k*3+0] += s[0] * w;
            acc[3+k*3+1] += s[1] * w;
            acc[3+k*3+2] += s[2] * w;
        }
    }
    #pragma unroll
    for (int m = 16; m > 0; m >>= 1)
        #pragma unroll
        for (int i = 0; i < 33; ++i)
            acc[i] += __shfl_xor_sync(0xffffffffu, acc[i], m);

    __shared__ float s[4][33];
    int wid = threadIdx.x >> 5, lane = threadIdx.x & 31;
    if (lane == 0)
        #pragma unroll
        for (int i = 0; i < 33; ++i) s[wid][i] = acc[i];
    __syncthreads();
    if (threadIdx.x < 33) {
        float t = s[0][threadIdx.x] + s[1][threadIdx.x] + s[2][threadIdx.x] + s[3][threadIdx.x];
        g_jmp[(j*8 + part)*33 + threadIdx.x] = t;
    }
}

__global__ void k_jmred()
{
    int i = blockIdx.x * blockDim.x + threadIdx.x;
    if (i < NJ * 33) {
        int jj = i / 33, r = i % 33;
        float t = 0.f;
        #pragma unroll
        for (int p = 0; p < 8; ++p) t += g_jmp[(jj*8 + p)*33 + r];
        g_jm[i] = t;
    }
}

// ---------------------------------------------------------------------------
// Kernel 1: fused Rodrigues + kinematic chain. 32 batches per block.
// ---------------------------------------------------------------------------
__global__ void __launch_bounds__(96) k_rotchain(const float* __restrict__ inp,
                                                 float* __restrict__ out)
{
    const int PAR[NJ] = {0,0,0,0,1,2,3,4,5,6,7,8,9,9,9,12,13,14,16,17,18,19,20,21};
    __shared__ float s_jm[NJ * 33];
    __shared__ float sJ[32][NJ*3];
    __shared__ float sR[32][NJ*9];

    const int tid = threadIdx.x;
    const int b0 = blockIdx.x * 32;

    for (int i = tid; i < NJ*33; i += 96) s_jm[i] = g_jm[i];

    for (int i = tid; i < 32*NJ; i += 96) {
        int bl = i / NJ, j = i % NJ;
        int b = b0 + bl;
        float rx = inp[b*82 + j*3 + 0];
        float ry = inp[b*82 + j*3 + 1];
        float rz = inp[b*82 + j*3 + 2];
        float ax = rx + 1e-8f, ay = ry + 1e-8f, az = rz + 1e-8f;
        float ang = sqrtf(ax*ax + ay*ay + az*az);
        float inv = 1.0f / ang;
        float nx = rx * inv, ny = ry * inv, nz = rz * inv;
        float c = cosf(ang), sn = sinf(ang), ic = 1.0f - c;
        float R[9];
        R[0] = c + ic*nx*nx;     R[1] = ic*nx*ny - sn*nz; R[2] = ic*nx*nz + sn*ny;
        R[3] = ic*ny*nx + sn*nz; R[4] = c + ic*ny*ny;     R[5] = ic*ny*nz - sn*nx;
        R[6] = ic*nz*nx - sn*ny; R[7] = ic*nz*ny + sn*nx; R[8] = c + ic*nz*nz;

        float* ro = out + ROT_OFF + (size_t)b*(NJ*9) + j*9;
        #pragma unroll
        for (int e = 0; e < 9; ++e) { ro[e] = R[e]; sR[bl][j*9+e] = R[e]; }

        if (j > 0) {
            int base = (j-1) * 9;
            #pragma unroll
            for (int e = 0; e < 9; ++e)
                g_pfT[(base + e) * BB + b] = R[e] - ((e==0||e==4||e==8) ? 1.0f : 0.0f);
        }
    }
    __syncthreads();

    for (int i = tid; i < 32*NJ*3; i += 96) {
        int bl = i / 72, rem = i % 72;
        int j = rem / 3, c = rem % 3;
        int b = b0 + bl;
        float t = s_jm[j*33 + c];
        #pragma unroll
        for (int k = 0; k < NBETA; ++k)
            t = fmaf(inp[b*82 + 72 + k], s_jm[j*33 + 3 + k*3 + c], t);
        sJ[bl][j*3 + c] = t;
    }
    __syncthreads();

    const int bl = tid / 3;
    const int r  = tid % 3;
    const int b  = b0 + bl;
    const float* Rb = sR[bl];

    float row[NJ][3];
    float tw[NJ];
    row[0][0] = Rb[r*3+0]; row[0][1] = Rb[r*3+1]; row[0][2] = Rb[r*3+2];
    tw[0] = sJ[bl][r];

    #pragma unroll
    for (int j = 1; j < NJ; ++j) {
        const int p = PAR[j];
        float t0 = sJ[bl][j*3+0] - sJ[bl][p*3+0];
        float t1 = sJ[bl][j*3+1] - sJ[bl][p*3+1];
        float t2 = sJ[bl][j*3+2] - sJ[bl][p*3+2];
        float p0 = row[p][0], p1 = row[p][1], p2 = row[p][2];
        row[j][0] = p0*Rb[j*9+0] + p1*Rb[j*9+3] + p2*Rb[j*9+6];
        row[j][1] = p0*Rb[j*9+1] + p1*Rb[j*9+4] + p2*Rb[j*9+7];
        row[j][2] = p0*Rb[j*9+2] + p1*Rb[j*9+5] + p2*Rb[j*9+8];
        tw[j] = p0*t0 + p1*t1 + p2*t2 + tw[p];
    }

    float* Ao = g_A + (size_t)b * (NJ*12);
    #pragma unroll
    for (int j = 0; j < NJ; ++j) {
        float tp = tw[j] - (row[j][0]*sJ[bl][j*3+0] + row[j][1]*sJ[bl][j*3+1] + row[j][2]*sJ[bl][j*3+2]);
        float4 st = make_float4(row[j][0], row[j][1], row[j][2], tp);
        *reinterpret_cast<float4*>(&Ao[j*12 + r*4]) = st;
    }

    if (r == 0) {
        #pragma unroll
        for (int k = 0; k < NBETA; ++k) g_pfT[(NP + k)*BB + b] = inp[b*82 + 72 + k];
        #pragma unroll
        for (int k = KTOT; k < KPAD; ++k) g_pfT[k*BB + b] = 0.0f;
    }
}

// ---------------------------------------------------------------------------
// Kernel 2: fused blendshape GEMM + LBS skinning.
// Tile: 64 batches x 96 cols, 128 threads, cp.async double-buffered.
// Layouts tuned for 4 conflict-free LDS wavefronts per k-iter:
//   d  : plane0 [k][16 cgrp][4f] (LDS.128) + plane1 [k][16 cgrp][2f] (LDS.64)
//   pf : u64 [k][8 bgrp][4 bp] permuted at cp.async time (2x LDS.128)
// w (stride 26, conflict-free) and vt prefetched via cp.async at start.
// ---------------------------------------------------------------------------
__global__ void __launch_bounds__(128, 4) k_main(const float* __restrict__ posedirs,
                                                 const float* __restrict__ shapes,
                                                 const float* __restrict__ lbs,
                                                 const float* __restrict__ vtempl,
                                                 float* __restrict__ out)
{
    __shared__ __align__(16) float smem[11168];
    float* s_d  = smem;           // 2 x 3072 (plane0 2048 + plane1 1024)
    float* s_pf = smem + 6144;    // 2 x 2048
    float* s_w  = smem + 10240;   // 32 x 26
    float* s_vt = smem + 11072;   // 96

    const int b0   = blockIdx.y * 64;
    const int col0 = blockIdx.x * 96;
    const int v0   = blockIdx.x * 32;
    const int tid  = threadIdx.x;
    const int lane = tid & 31;
    const int warp = tid >> 5;
    const int cgrp = (lane & 7) + ((warp & 1) << 3);   // 0..15
    const int bgrp = (lane >> 3) + ((warp >> 1) << 2); // 0..7

    const unsigned sd_base  = (unsigned)__cvta_generic_to_shared(s_d);
    const unsigned spf_base = (unsigned)__cvta_generic_to_shared(s_pf);
    const unsigned sw_base  = (unsigned)__cvta_generic_to_shared(s_w);
    const unsigned svt_base = (unsigned)__cvta_generic_to_shared(s_vt);

    auto load_tiles = [&](int kt, int buf) {
        // d tile: 1536 col-pair chunks of 8B
        #pragma unroll
        for (int it = 0; it < 12; ++it) {
            int i = tid + it*128;
            int k = i / 48, q = i % 48;
            int cgd = q / 3, slot = q % 3;
            int kg = kt*32 + k;
            int cg = col0 + q*2;
            const float* src = posedirs;
            int sz = 0;
            if (cg < VC && kg < KTOT) {
                sz = 8;
                src = (kg < NP) ? posedirs + (size_t)kg*VC + cg
                                : shapes + (size_t)(kg-NP)*VC + cg;
            }
            unsigned ds = (slot < 2)
                ? (unsigned)(buf*3072 + k*64 + cgd*4 + slot*2)
                : (unsigned)(buf*3072 + 2048 + k*32 + cgd*2);
            cp_async8(sd_base + ds*4u, src, sz);
        }
        // pf tile: 1024 batch-pair u64s, permuted [k][bgrp][bp]
        #pragma unroll
        for (int it = 0; it < 8; ++it) {
            int i = tid + it*128;
            int k = i >> 5, pp = i & 31;
            unsigned du = (unsigned)(k*32 + (pp & 7)*4 + (pp >> 3));
            cp_async8(spf_base + (unsigned)buf*8192u + du*8u,
                      &g_pfT[(kt*32 + k)*BB + b0 + 2*pp], 8);
        }
        cp_commit();
    };

    // prefetch w (lbs weights, padded stride 26) and vt — same first group
    #pragma unroll
    for (int it = 0; it < 3; ++it) {
        int i = tid + it*128;            // 0..383 pairs
        int vl = (i*2) / 24, j = (i*2) % 24;
        int v = v0 + vl;
        cp_async8(sw_base + (unsigned)(vl*26 + j)*4u,
                  lbs + (size_t)v*NJ + j, (v < VV) ? 8 : 0);
    }
    if (tid < 48) {
        int cg = col0 + tid*2;
        cp_async8(svt_base + (unsigned)tid*8u, vtempl + cg, (cg < VC) ? 8 : 0);
    }
    load_tiles(0, 0);

    u64 acc[24];                       // [cc*4+bp], batch pairs packed
    const u64 z2 = pack2(0.f, 0.f);
    #pragma unroll
    for (int i = 0; i < 24; ++i) acc[i] = z2;

    for (int kt = 0; kt < 7; ++kt) {
        const int buf = kt & 1;
        if (kt < 6) load_tiles(kt+1, buf ^ 1);
        if (kt < 6) cp_wait<1>(); else cp_wait<0>();
        __syncthreads();

        const float4* dp0 = reinterpret_cast<const float4*>(s_d + buf*3072) + cgrp;
        const float2* dp1 = reinterpret_cast<const float2*>(s_d + buf*3072 + 2048) + cgrp;
        const ulonglong2* pfp = reinterpret_cast<const ulonglong2*>(s_pf + buf*2048) + bgrp*2;

        #pragma unroll
        for (int k = 0; k < 32; ++k) {
            float4 dA = dp0[k*16];
            float2 dB = dp1[k*16];
            ulonglong2 P01 = pfp[k*16];
            ulonglong2 P23 = pfp[k*16 + 1];
            u64 p0 = P01.x, p1 = P01.y, p2 = P23.x, p3 = P23.y;
            u64 dd0 = pack2(dA.x, dA.x), dd1 = pack2(dA.y, dA.y);
            u64 dd2 = pack2(dA.z, dA.z), dd3 = pack2(dA.w, dA.w);
            u64 dd4 = pack2(dB.x, dB.x), dd5 = pack2(dB.y, dB.y);
            acc[0]  = ffma2(p0, dd0, acc[0]);
            acc[1]  = ffma2(p1, dd0, acc[1]);
            acc[2]  = ffma2(p2, dd0, acc[2]);
            acc[3]  = ffma2(p3, dd0, acc[3]);
            acc[4]  = ffma2(p0, dd1, acc[4]);
            acc[5]  = ffma2(p1, dd1, acc[5]);
            acc[6]  = ffma2(p2, dd1, acc[6]);
            acc[7]  = ffma2(p3, dd1, acc[7]);
            acc[8]  = ffma2(p0, dd2, acc[8]);
            acc[9]  = ffma2(p1, dd2, acc[9]);
            acc[10] = ffma2(p2, dd2, acc[10]);
            acc[11] = ffma2(p3, dd2, acc[11]);
            acc[12] = ffma2(p0, dd3, acc[12]);
            acc[13] = ffma2(p1, dd3, acc[13]);
            acc[14] = ffma2(p2, dd3, acc[14]);
            acc[15] = ffma2(p3, dd3, acc[15]);
            acc[16] = ffma2(p0, dd4, acc[16]);
            acc[17] = ffma2(p1, dd4, acc[17]);
            acc[18] = ffma2(p2, dd4, acc[18]);
            acc[19] = ffma2(p3, dd4, acc[19]);
            acc[20] = ffma2(p0, dd5, acc[20]);
            acc[21] = ffma2(p1, dd5, acc[21]);
            acc[22] = ffma2(p2, dd5, acc[22]);
            acc[23] = ffma2(p3, dd5, acc[23]);
        }
        __syncthreads();
    }

    // ---- epilogue ----
    const int v0l = cgrp * 2;
    const int vg0 = v0 + v0l;
    const int vg1 = vg0 + 1;

    #pragma unroll
    for (int pass = 0; pass < 2; ++pass) {
        __syncthreads();
        const float4* gA4 = reinterpret_cast<const float4*>(g_A + (size_t)(b0 + pass*32)*288);
        #pragma unroll
        for (int i = 0; i < 18; ++i)
            reinterpret_cast<float4*>(smem)[tid + 128*i] = gA4[tid + 128*i];
        __syncthreads();

        #pragma unroll
        for (int bpi = 0; bpi < 2; ++bpi) {
            const int bp = pass*2 + bpi;
            #pragma unroll
            for (int half = 0; half < 2; ++half) {
                const int ab = 2*bgrp + 16*bpi + half;
                const int b = b0 + pass*32 + ab;
                const ulonglong2* Ar2 = reinterpret_cast<const ulonglong2*>(smem + ab*288);
                u64 T0[6], T1[6];
                #pragma unroll
                for (int i = 0; i < 6; ++i) { T0[i] = z2; T1[i] = z2; }
                #pragma unroll
                for (int j = 0; j < NJ; ++j) {
                    ulonglong2 A01 = Ar2[j*3 + 0];
                    ulonglong2 A23 = Ar2[j*3 + 1];
                    ulonglong2 A45 = Ar2[j*3 + 2];
                    float w0 = s_w[(v0l + 0)*26 + j];
                    float w1 = s_w[(v0l + 1)*26 + j];
                    u64 w0d = pack2(w0, w0);
                    u64 w1d = pack2(w1, w1);
                    T0[0] = ffma2(w0d, A01.x, T0[0]); T0[1] = ffma2(w0d, A01.y, T0[1]);
                    T0[2] = ffma2(w0d, A23.x, T0[2]); T0[3] = ffma2(w0d, A23.y, T0[3]);
                    T0[4] = ffma2(w0d, A45.x, T0[4]); T0[5] = ffma2(w0d, A45.y, T0[5]);
                    T1[0] = ffma2(w1d, A01.x, T1[0]); T1[1] = ffma2(w1d, A01.y, T1[1]);
                    T1[2] = ffma2(w1d, A23.x, T1[2]); T1[3] = ffma2(w1d, A23.y, T1[3]);
                    T1[4] = ffma2(w1d, A45.x, T1[4]); T1[5] = ffma2(w1d, A45.y, T1[5]);
                }
                if (vg0 < VV) {
                    float2 c0 = unpack2(acc[0*4+bp]);
                    float2 c1 = unpack2(acc[1*4+bp]);
                    float2 c2 = unpack2(acc[2*4+bp]);
                    float x = (half ? c0.y : c0.x) + s_vt[cgrp*6+0];
                    float y = (half ? c1.y : c1.x) + s_vt[cgrp*6+1];
                    float z = (half ? c2.y : c2.x) + s_vt[cgrp*6+2];
                    float2 r0 = unpack2(T0[0]), r1 = unpack2(T0[1]);
                    float2 r2 = unpack2(T0[2]), r3 = unpack2(T0[3]);
                    float2 r4 = unpack2(T0[4]), r5 = unpack2(T0[5]);
                    float* o = out + (size_t)b*VC + vg0*3;
                    o[0] = r0.x*x + r0.y*y + r1.x*z + r1.y;
                    o[1] = r2.x*x + r2.y*y + r3.x*z + r3.y;
                    o[2] = r4.x*x + r4.y*y + r5.x*z + r5.y;
                }
                if (vg1 < VV) {
                    float2 c3 = unpack2(acc[3*4+bp]);
                    float2 c4 = unpack2(acc[4*4+bp]);
                    float2 c5 = unpack2(acc[5*4+bp]);
                    float x = (half ? c3.y : c3.x) + s_vt[cgrp*6+3];
                    float y = (half ? c4.y : c4.x) + s_vt[cgrp*6+4];
                    float z = (half ? c5.y : c5.x) + s_vt[cgrp*6+5];
                    float2 r0 = unpack2(T1[0]), r1 = unpack2(T1[1]);
                    float2 r2 = unpack2(T1[2]), r3 = unpack2(T1[3]);
                    float2 r4 = unpack2(T1[4]), r5 = unpack2(T1[5]);
                    float* o = out + (size_t)b*VC + vg1*3;
                    o[0] = r0.x*x + r0.y*y + r1.x*z + r1.y;
                    o[1] = r2.x*x + r2.y*y + r3.x*z + r3.y;
                    o[2] = r4.x*x + r4.y*y + r5.x*z + r5.y;
                }
            }
        }
    }
}

// ---------------------------------------------------------------------------
// Kernel 3: joints = vertices @ joint_regressor (deterministic 2-stage)
// ---------------------------------------------------------------------------
__global__ void __launch_bounds__(256) k_jnt_part(const float* __restrict__ outv,
                                                  const float* __restrict__ jreg)
{
    __shared__ float s_jr[512 * NJO];
    const int chunk = blockIdx.x;
    const int v0 = chunk * 512;
    for (int i = threadIdx.x; i < 512*NJO; i += 256) {
        int v = v0 + i / NJO;
        s_jr[i] = (v < VV) ? jreg[v*NJO + (i % NJO)] : 0.f;
    }
    __syncthreads();

    const int bl = threadIdx.x >> 5, lane = threadIdx.x & 31;
    const int b = blockIdx.y * 8 + bl;

    float acc[57];
    #pragma unroll
    for (int i = 0; i < 57; ++i) acc[i] = 0.f;

    #pragma unroll 4
    for (int i = 0; i < 16; ++i) {
        int vl = lane + i*32;
        int vg = v0 + vl;
        if (vg < VV) {
            const float* p = outv + (size_t)b*VC + vg*3;
            float x = p[0], y = p[1], z = p[2];
            #pragma unroll
            for (int j = 0; j < NJO; ++j) {
                float r = s_jr[vl*NJO + j];
                acc[j*3+0] = fmaf(r, x, acc[j*3+0]);
                acc[j*3+1] = fmaf(r, y, acc[j*3+1]);
                acc[j*3+2] = fmaf(r, z, acc[j*3+2]);
            }
        }
    }
    #pragma unroll
    for (int m = 16; m > 0; m >>= 1)
        #pragma unroll
        for (int i = 0; i < 57; ++i)
            acc[i] += __shfl_xor_sync(0xffffffffu, acc[i], m);

    if (lane == 0) {
        float* dst = g_jpart + (size_t)(b*14 + chunk)*57;
        #pragma unroll
        for (int i = 0; i < 57; ++i) dst[i] = acc[i];
    }
}

__global__ void k_jnt_red(float* __restrict__ out)
{
    int i = blockIdx.x * blockDim.x + threadIdx.x;
    if (i < BB * 57) {
        int b = i / 57, r = i % 57;
        float t = 0.f;
        #pragma unroll
        for (int p = 0; p < 14; ++p) t += g_jpart[(size_t)(b*14 + p)*57 + r];
        out[JNT_OFF + i] = t;
    }
}

// ---------------------------------------------------------------------------
extern "C" void kernel_launch(void* const* d_in, const int* in_sizes, int n_in,
                              void* d_out, int out_size)
{
    const float* inputs   = (const float*)d_in[0];
    const float* v_templ  = (const float*)d_in[1];
    const float* shapes   = (const float*)d_in[2];
    const float* posedirs = (const float*)d_in[3];
    const float* smpl_reg = (const float*)d_in[4];
    const float* lbs_w    = (const float*)d_in[5];
    const float* joint_rg = (const float*)d_in[6];
    float* out = (float*)d_out;

    k_jm<<<dim3(NJ, 8), 128>>>(v_templ, shapes, smpl_reg);
    k_jmred<<<4, 256>>>();

    k_rotchain<<<16, 96>>>(inputs, out);

    k_main<<<dim3(216, 8), 128>>>(posedirs, shapes, lbs_w, v_templ, out);

    k_jnt_part<<<dim3(14, 64), 256>>>(out, joint_rg);
    k_jnt_red<<<(BB*57 + 255)/256, 256>>>(out);
}

// round 8
// speedup vs baseline: 1.2632x; 1.2632x over previous
#include <cuda_runtime.h>
#include <cuda_bf16.h>
#include <math.h>

// ---------------------------------------------------------------------------
#define BB 512
#define VV 6890
#define NJ 24
#define NBETA 10
#define NP 207
#define NJO 19
#define VC (VV*3)              // 20670
#define KTOT 217
#define KPAD 224               // 7*32
#define JNT_OFF  (BB*VC)
#define ROT_OFF  (JNT_OFF + BB*NJO*3)

typedef unsigned long long u64;

__device__ __forceinline__ u64 ffma2(u64 a, u64 b, u64 c) {
    u64 d;
    asm("fma.rn.f32x2 %0, %1, %2, %3;" : "=l"(d) : "l"(a), "l"(b), "l"(c));
    return d;
}
__device__ __forceinline__ u64 pack2(float lo, float hi) {
    u64 d;
    asm("mov.b64 %0, {%1, %2};" : "=l"(d) : "f"(lo), "f"(hi));
    return d;
}
__device__ __forceinline__ float2 unpack2(u64 v) {
    float2 f;
    asm("mov.b64 {%0, %1}, %2;" : "=f"(f.x), "=f"(f.y) : "l"(v));
    return f;
}
__device__ __forceinline__ void cp_async8(unsigned saddr, const void* gaddr, int srcsize) {
    asm volatile("cp.async.ca.shared.global [%0], [%1], 8, %2;"
                 :: "r"(saddr), "l"(gaddr), "r"(srcsize));
}
__device__ __forceinline__ void cp_async16(unsigned saddr, const void* gaddr) {
    asm volatile("cp.async.ca.shared.global [%0], [%1], 16;"
                 :: "r"(saddr), "l"(gaddr));
}
__device__ __forceinline__ void cp_commit() {
    asm volatile("cp.async.commit_group;");
}
template<int N>
__device__ __forceinline__ void cp_wait() {
    asm volatile("cp.async.wait_group %0;" :: "n"(N));
}
// round f32 -> tf32 (RNA), result kept in an f32 container
__device__ __forceinline__ float tf32r(float x) {
    unsigned u;
    asm("cvt.rna.tf32.f32 %0, %1;" : "=r"(u) : "f"(x));
    return __uint_as_float(u);
}
__device__ __forceinline__ unsigned tf32u(float x) {
    unsigned u;
    asm("cvt.rna.tf32.f32 %0, %1;" : "=r"(u) : "f"(x));
    return u;
}
// m16n8k8 tf32 MMA: C += A*B (fragments per PTX layout)
__device__ __forceinline__ void mma_tf32(float* c, const unsigned* a, unsigned b0, unsigned b1) {
    asm("mma.sync.aligned.m16n8k8.row.col.f32.tf32.tf32.f32 "
        "{%0,%1,%2,%3},{%4,%5,%6,%7},{%8,%9},{%0,%1,%2,%3};"
        : "+f"(c[0]), "+f"(c[1]), "+f"(c[2]), "+f"(c[3])
        : "r"(a[0]), "r"(a[1]), "r"(a[2]), "r"(a[3]), "r"(b0), "r"(b1));
}

// ---------------------------------------------------------------------------
__device__ float g_pfT[KPAD * BB];        // pose-feature+beta (tf32-rounded), [k][b]
__device__ float g_A[BB * NJ * 12];       // A' 3x4 per (b,j)
__device__ float g_jmp[NJ * 8 * 33];
__device__ float g_jm[NJ * 33];
__device__ float g_jpart[BB * 14 * 57];

// ---------------------------------------------------------------------------
// Kernel 0: batch-independent precompute for rest joints
// ---------------------------------------------------------------------------
__global__ void __launch_bounds__(128) k_jm(const float* __restrict__ vt,
                                            const float* __restrict__ shp,
                                            const float* __restrict__ sr)
{
    int j = blockIdx.x, part = blockIdx.y;
    int vs = part * 862;
    int ve = vs + 862; if (ve > VV) ve = VV;

    float acc[33];
    #pragma unroll
    for (int i = 0; i < 33; ++i) acc[i] = 0.f;

    for (int v = vs + threadIdx.x; v < ve; v += 128) {
        float w = sr[v * NJ + j];
        acc[0] += vt[v*3+0] * w;
        acc[1] += vt[v*3+1] * w;
        acc[2] += vt[v*3+2] * w;
        #pragma unroll
        for (int k = 0; k < NBETA; ++k) {
            const float* s = shp + k * VC + v * 3;
            acc[3+k*3+0] += s[0] * w;
            acc[3+k*3+1] += s[1] * w;
            acc[3+k*3+2] += s[2] * w;
        }
    }
    #pragma unroll
    for (int m = 16; m > 0; m >>= 1)
        #pragma unroll
        for (int i = 0; i < 33; ++i)
            acc[i] += __shfl_xor_sync(0xffffffffu, acc[i], m);

    __shared__ float s[4][33];
    int wid = threadIdx.x >> 5, lane = threadIdx.x & 31;
    if (lane == 0)
        #pragma unroll
        for (int i = 0; i < 33; ++i) s[wid][i] = acc[i];
    __syncthreads();
    if (threadIdx.x < 33) {
        float t = s[0][threadIdx.x] + s[1][threadIdx.x] + s[2][threadIdx.x] + s[3][threadIdx.x];
        g_jmp[(j*8 + part)*33 + threadIdx.x] = t;
    }
}

__global__ void k_jmred()
{
    int i = blockIdx.x * blockDim.x + threadIdx.x;
    if (i < NJ * 33) {
        int jj = i / 33, r = i % 33;
        float t = 0.f;
        #pragma unroll
        for (int p = 0; p < 8; ++p) t += g_jmp[(jj*8 + p)*33 + r];
        g_jm[i] = t;
    }
}

// ---------------------------------------------------------------------------
// Kernel 1: fused Rodrigues + kinematic chain. 32 batches per block.
// pose-feature rows are pre-rounded to tf32 at the source.
// ---------------------------------------------------------------------------
__global__ void __launch_bounds__(96) k_rotchain(const float* __restrict__ inp,
                                                 float* __restrict__ out)
{
    const int PAR[NJ] = {0,0,0,0,1,2,3,4,5,6,7,8,9,9,9,12,13,14,16,17,18,19,20,21};
    __shared__ float s_jm[NJ * 33];
    __shared__ float sJ[32][NJ*3];
    __shared__ float sR[32][NJ*9];

    const int tid = threadIdx.x;
    const int b0 = blockIdx.x * 32;

    for (int i = tid; i < NJ*33; i += 96) s_jm[i] = g_jm[i];

    for (int i = tid; i < 32*NJ; i += 96) {
        int bl = i / NJ, j = i % NJ;
        int b = b0 + bl;
        float rx = inp[b*82 + j*3 + 0];
        float ry = inp[b*82 + j*3 + 1];
        float rz = inp[b*82 + j*3 + 2];
        float ax = rx + 1e-8f, ay = ry + 1e-8f, az = rz + 1e-8f;
        float ang = sqrtf(ax*ax + ay*ay + az*az);
        float inv = 1.0f / ang;
        float nx = rx * inv, ny = ry * inv, nz = rz * inv;
        float c = cosf(ang), sn = sinf(ang), ic = 1.0f - c;
        float R[9];
        R[0] = c + ic*nx*nx;     R[1] = ic*nx*ny - sn*nz; R[2] = ic*nx*nz + sn*ny;
        R[3] = ic*ny*nx + sn*nz; R[4] = c + ic*ny*ny;     R[5] = ic*ny*nz - sn*nx;
        R[6] = ic*nz*nx - sn*ny; R[7] = ic*nz*ny + sn*nx; R[8] = c + ic*nz*nz;

        float* ro = out + ROT_OFF + (size_t)b*(NJ*9) + j*9;
        #pragma unroll
        for (int e = 0; e < 9; ++e) { ro[e] = R[e]; sR[bl][j*9+e] = R[e]; }

        if (j > 0) {
            int base = (j-1) * 9;
            #pragma unroll
            for (int e = 0; e < 9; ++e)
                g_pfT[(base + e) * BB + b] = tf32r(R[e] - ((e==0||e==4||e==8) ? 1.0f : 0.0f));
        }
    }
    __syncthreads();

    for (int i = tid; i < 32*NJ*3; i += 96) {
        int bl = i / 72, rem = i % 72;
        int j = rem / 3, c = rem % 3;
        int b = b0 + bl;
        float t = s_jm[j*33 + c];
        #pragma unroll
        for (int k = 0; k < NBETA; ++k)
            t = fmaf(inp[b*82 + 72 + k], s_jm[j*33 + 3 + k*3 + c], t);
        sJ[bl][j*3 + c] = t;
    }
    __syncthreads();

    const int bl = tid / 3;
    const int r  = tid % 3;
    const int b  = b0 + bl;
    const float* Rb = sR[bl];

    float row[NJ][3];
    float tw[NJ];
    row[0][0] = Rb[r*3+0]; row[0][1] = Rb[r*3+1]; row[0][2] = Rb[r*3+2];
    tw[0] = sJ[bl][r];

    #pragma unroll
    for (int j = 1; j < NJ; ++j) {
        const int p = PAR[j];
        float t0 = sJ[bl][j*3+0] - sJ[bl][p*3+0];
        float t1 = sJ[bl][j*3+1] - sJ[bl][p*3+1];
        float t2 = sJ[bl][j*3+2] - sJ[bl][p*3+2];
        float p0 = row[p][0], p1 = row[p][1], p2 = row[p][2];
        row[j][0] = p0*Rb[j*9+0] + p1*Rb[j*9+3] + p2*Rb[j*9+6];
        row[j][1] = p0*Rb[j*9+1] + p1*Rb[j*9+4] + p2*Rb[j*9+7];
        row[j][2] = p0*Rb[j*9+2] + p1*Rb[j*9+5] + p2*Rb[j*9+8];
        tw[j] = p0*t0 + p1*t1 + p2*t2 + tw[p];
    }

    float* Ao = g_A + (size_t)b * (NJ*12);
    #pragma unroll
    for (int j = 0; j < NJ; ++j) {
        float tp = tw[j] - (row[j][0]*sJ[bl][j*3+0] + row[j][1]*sJ[bl][j*3+1] + row[j][2]*sJ[bl][j*3+2]);
        float4 st = make_float4(row[j][0], row[j][1], row[j][2], tp);
        *reinterpret_cast<float4*>(&Ao[j*12 + r*4]) = st;
    }

    if (r == 0) {
        #pragma unroll
        for (int k = 0; k < NBETA; ++k) g_pfT[(NP + k)*BB + b] = tf32r(inp[b*82 + 72 + k]);
        #pragma unroll
        for (int k = KTOT; k < KPAD; ++k) g_pfT[k*BB + b] = 0.0f;
    }
}

// ---------------------------------------------------------------------------
// Kernel 2: blendshape GEMM on TENSOR CORES (mma.sync m16n8k8 tf32) fused
// with LBS skinning epilogue (FFMA2).
// Tile: 64 batches x 96 cols, 256 threads (8 warps = 4 warp_m x 2 warp_n).
// Each warp: M=16 (1 m-frag) x N=48 (6 n-frags), K=224 (28 k-steps).
// smem (floats): s_d 2x[32][104] @0 (6656) | s_pf 2x[32][72] @6656 (4608)
//   epilogue alias: s_A @0 (16x288=4608), s_vp @4608 (16x96=1536)
//   dedicated: s_w @11264 (32x25=800), s_vt @12064 (96)  -> total 12160 f
// pf stride 72, d stride 104: (k*8+idx)&31 distinct => conflict-free frags.
// ---------------------------------------------------------------------------
__global__ void __launch_bounds__(256, 2) k_main(const float* __restrict__ posedirs,
                                                 const float* __restrict__ shapes,
                                                 const float* __restrict__ lbs,
                                                 const float* __restrict__ vtempl,
                                                 float* __restrict__ out)
{
    __shared__ __align__(16) float smem[12160];
    float* s_d  = smem;            // buf*3328
    float* s_pf = smem + 6656;     // buf*2304
    float* s_A  = smem;            // epilogue alias
    float* s_vp = smem + 4608;     // epilogue alias
    float* s_w  = smem + 11264;    // [32][25]
    float* s_vt = smem + 12064;    // [96]

    const int b0   = blockIdx.y * 64;
    const int col0 = blockIdx.x * 96;
    const int v0   = blockIdx.x * 32;
    const int tid  = threadIdx.x;
    const int lane = tid & 31;
    const int warp = tid >> 5;
    const int warp_m = warp >> 1;     // 0..3 -> 16 batches each
    const int warp_n = warp & 1;      // 0..1 -> 48 cols each
    const int g  = lane >> 2;         // 0..7
    const int tg = lane & 3;          // 0..3

    const unsigned sd_base  = (unsigned)__cvta_generic_to_shared(s_d);
    const unsigned spf_base = (unsigned)__cvta_generic_to_shared(s_pf);

    auto load_tiles = [&](int kt, int buf) {
        // d tile: 32 k-rows x 48 col-pairs (8B each)
        #pragma unroll
        for (int it = 0; it < 6; ++it) {
            int i = tid + it*256;
            int k = i / 48, q = i % 48;
            int kg = kt*32 + k;
            int cg = col0 + q*2;
            const float* src = posedirs;
            int sz = 0;
            if (cg < VC && kg < KTOT) {
                sz = 8;
                src = (kg < NP) ? posedirs + (size_t)kg*VC + cg
                                : shapes + (size_t)(kg-NP)*VC + cg;
            }
            cp_async8(sd_base + (unsigned)(buf*3328 + k*104 + q*2)*4u, src, sz);
        }
        // pf tile: 32 k-rows x 16 float4 (64 batches)
        #pragma unroll
        for (int it = 0; it < 2; ++it) {
            int i = tid + it*256;
            int k = i >> 4, q = i & 15;
            cp_async16(spf_base + (unsigned)(buf*2304 + k*72 + q*4)*4u,
                       &g_pfT[(kt*32 + k)*BB + b0 + q*4]);
        }
        cp_commit();
    };

    float c[6][4];
    #pragma unroll
    for (int i = 0; i < 6; ++i)
        #pragma unroll
        for (int e = 0; e < 4; ++e) c[i][e] = 0.f;

    load_tiles(0, 0);

    for (int kt = 0; kt < 7; ++kt) {
        const int buf = kt & 1;
        if (kt < 6) load_tiles(kt+1, buf ^ 1);
        if (kt < 6) cp_wait<1>(); else cp_wait<0>();
        __syncthreads();

        const float* pa = s_pf + buf*2304 + tg*72 + warp_m*16 + g;
        const float* pb = s_d  + buf*3328 + tg*104 + warp_n*48 + g;

        #pragma unroll
        for (int ks = 0; ks < 4; ++ks) {
            const float* pak = pa + ks*576;   // ks*8*72
            const float* pbk = pb + ks*832;   // ks*8*104
            unsigned a[4];
            a[0] = __float_as_uint(pak[0]);        // row g,   k tg   (pre-rounded)
            a[1] = __float_as_uint(pak[8]);        // row g+8, k tg
            a[2] = __float_as_uint(pak[288]);      // row g,   k tg+4 (4*72)
            a[3] = __float_as_uint(pak[296]);      // row g+8, k tg+4
            #pragma unroll
            for (int nt = 0; nt < 6; ++nt) {
                unsigned bb0 = tf32u(pbk[nt*8]);          // k tg,   n g
                unsigned bb1 = tf32u(pbk[nt*8 + 416]);    // k tg+4, n g  (4*104)
                mma_tf32(c[nt], a, bb0, bb1);
            }
        }
        __syncthreads();
    }

    // ---- epilogue: LBS skinning ----
    // load weights (stride 25: conflict-free) and template cols
    for (int i = tid; i < 768; i += 256) {
        int vl = i / 24, j = i % 24;
        int v = v0 + vl;
        s_w[vl*25 + j] = (v < VV) ? lbs[(size_t)v*NJ + j] : 0.f;
    }
    if (tid < 96) {
        int cg = col0 + tid;
        s_vt[tid] = (cg < VC) ? vtempl[cg] : 0.f;
    }

    const u64 z2 = pack2(0.f, 0.f);
    const int tv = tid & 15;      // vert pair -> verts tv*2, tv*2+1
    const int tb = tid >> 4;      // 0..15 -> one batch per pass
    const int vg0 = v0 + tv*2;
    const int vg1 = vg0 + 1;

    #pragma unroll
    for (int pass = 0; pass < 4; ++pass) {
        __syncthreads();
        // (a) warps owning this pass's 16 batches dump C (+vt) into s_vp
        if (warp_m == pass) {
            #pragma unroll
            for (int nt = 0; nt < 6; ++nt) {
                int colL = warp_n*48 + nt*8 + tg*2;
                float vt0 = s_vt[colL], vt1 = s_vt[colL+1];
                s_vp[g*96 + colL]        = c[nt][0] + vt0;
                s_vp[g*96 + colL + 1]    = c[nt][1] + vt1;
                s_vp[(g+8)*96 + colL]    = c[nt][2] + vt0;
                s_vp[(g+8)*96 + colL+1]  = c[nt][3] + vt1;
            }
        }
        // (b) stage A' for 16 batches (4608 f)
        {
            const float4* gA4 = reinterpret_cast<const float4*>(g_A + (size_t)(b0 + pass*16)*288);
            #pragma unroll
            for (int i = 0; i < 5; ++i) {
                int idx = tid + i*256;
                if (idx < 1152) reinterpret_cast<float4*>(s_A)[idx] = gA4[idx];
            }
        }
        __syncthreads();

        // (c) skin: each thread 1 batch x 2 verts
        const int b = b0 + pass*16 + tb;
        const ulonglong2* Ar2 = reinterpret_cast<const ulonglong2*>(s_A + tb*288);
        u64 T0[6], T1[6];
        #pragma unroll
        for (int i = 0; i < 6; ++i) { T0[i] = z2; T1[i] = z2; }
        #pragma unroll
        for (int j = 0; j < NJ; ++j) {
            ulonglong2 A01 = Ar2[j*3 + 0];
            ulonglong2 A23 = Ar2[j*3 + 1];
            ulonglong2 A45 = Ar2[j*3 + 2];
            float w0 = s_w[(tv*2 + 0)*25 + j];
            float w1 = s_w[(tv*2 + 1)*25 + j];
            u64 w0d = pack2(w0, w0);
            u64 w1d = pack2(w1, w1);
            T0[0] = ffma2(w0d, A01.x, T0[0]); T0[1] = ffma2(w0d, A01.y, T0[1]);
            T0[2] = ffma2(w0d, A23.x, T0[2]); T0[3] = ffma2(w0d, A23.y, T0[3]);
            T0[4] = ffma2(w0d, A45.x, T0[4]); T0[5] = ffma2(w0d, A45.y, T0[5]);
            T1[0] = ffma2(w1d, A01.x, T1[0]); T1[1] = ffma2(w1d, A01.y, T1[1]);
            T1[2] = ffma2(w1d, A23.x, T1[2]); T1[3] = ffma2(w1d, A23.y, T1[3]);
            T1[4] = ffma2(w1d, A45.x, T1[4]); T1[5] = ffma2(w1d, A45.y, T1[5]);
        }
        if (vg0 < VV) {
            float x = s_vp[tb*96 + tv*6 + 0];
            float y = s_vp[tb*96 + tv*6 + 1];
            float z = s_vp[tb*96 + tv*6 + 2];
            float2 r0 = unpack2(T0[0]), r1 = unpack2(T0[1]);
            float2 r2 = unpack2(T0[2]), r3 = unpack2(T0[3]);
            float2 r4 = unpack2(T0[4]), r5 = unpack2(T0[5]);
            float* o = out + (size_t)b*VC + vg0*3;
            o[0] = r0.x*x + r0.y*y + r1.x*z + r1.y;
            o[1] = r2.x*x + r2.y*y + r3.x*z + r3.y;
            o[2] = r4.x*x + r4.y*y + r5.x*z + r5.y;
        }
        if (vg1 < VV) {
            float x = s_vp[tb*96 + tv*6 + 3];
            float y = s_vp[tb*96 + tv*6 + 4];
            float z = s_vp[tb*96 + tv*6 + 5];
            float2 r0 = unpack2(T1[0]), r1 = unpack2(T1[1]);
            float2 r2 = unpack2(T1[2]), r3 = unpack2(T1[3]);
            float2 r4 = unpack2(T1[4]), r5 = unpack2(T1[5]);
            float* o = out + (size_t)b*VC + vg1*3;
            o[0] = r0.x*x + r0.y*y + r1.x*z + r1.y;
            o[1] = r2.x*x + r2.y*y + r3.x*z + r3.y;
            o[2] = r4.x*x + r4.y*y + r5.x*z + r5.y;
        }
    }
}

// ---------------------------------------------------------------------------
// Kernel 3: joints = vertices @ joint_regressor (deterministic 2-stage)
// ---------------------------------------------------------------------------
__global__ void __launch_bounds__(256) k_jnt_part(const float* __restrict__ outv,
                                                  const float* __restrict__ jreg)
{
    __shared__ float s_jr[512 * NJO];
    const int chunk = blockIdx.x;
    const int v0 = chunk * 512;
    for (int i = threadIdx.x; i < 512*NJO; i += 256) {
        int v = v0 + i / NJO;
        s_jr[i] = (v < VV) ? jreg[v*NJO + (i % NJO)] : 0.f;
    }
    __syncthreads();

    const int bl = threadIdx.x >> 5, lane = threadIdx.x & 31;
    const int b = blockIdx.y * 8 + bl;

    float acc[57];
    #pragma unroll
    for (int i = 0; i < 57; ++i) acc[i] = 0.f;

    #pragma unroll 4
    for (int i = 0; i < 16; ++i) {
        int vl = lane + i*32;
        int vg = v0 + vl;
        if (vg < VV) {
            const float* p = outv + (size_t)b*VC + vg*3;
            float x = p[0], y = p[1], z = p[2];
            #pragma unroll
            for (int j = 0; j < NJO; ++j) {
                float r = s_jr[vl*NJO + j];
                acc[j*3+0] = fmaf(r, x, acc[j*3+0]);
                acc[j*3+1] = fmaf(r, y, acc[j*3+1]);
                acc[j*3+2] = fmaf(r, z, acc[j*3+2]);
            }
        }
    }
    #pragma unroll
    for (int m = 16; m > 0; m >>= 1)
        #pragma unroll
        for (int i = 0; i < 57; ++i)
            acc[i] += __shfl_xor_sync(0xffffffffu, acc[i], m);

    if (lane == 0) {
        float* dst = g_jpart + (size_t)(b*14 + chunk)*57;
        #pragma unroll
        for (int i = 0; i < 57; ++i) dst[i] = acc[i];
    }
}

__global__ void k_jnt_red(float* __restrict__ out)
{
    int i = blockIdx.x * blockDim.x + threadIdx.x;
    if (i < BB * 57) {
        int b = i / 57, r = i % 57;
        float t = 0.f;
        #pragma unroll
        for (int p = 0; p < 14; ++p) t += g_jpart[(size_t)(b*14 + p)*57 + r];
        out[JNT_OFF + i] = t;
    }
}

// ---------------------------------------------------------------------------
extern "C" void kernel_launch(void* const* d_in, const int* in_sizes, int n_in,
                              void* d_out, int out_size)
{
    const float* inputs   = (const float*)d_in[0];
    const float* v_templ  = (const float*)d_in[1];
    const float* shapes   = (const float*)d_in[2];
    const float* posedirs = (const float*)d_in[3];
    const float* smpl_reg = (const float*)d_in[4];
    const float* lbs_w    = (const float*)d_in[5];
    const float* joint_rg = (const float*)d_in[6];
    float* out = (float*)d_out;

    k_jm<<<dim3(NJ, 8), 128>>>(v_templ, shapes, smpl_reg);
    k_jmred<<<4, 256>>>();

    k_rotchain<<<16, 96>>>(inputs, out);

    k_main<<<dim3(216, 8), 256>>>(posedirs, shapes, lbs_w, v_templ, out);

    k_jnt_part<<<dim3(14, 64), 256>>>(out, joint_rg);
    k_jnt_red<<<(BB*57 + 255)/256, 256>>>(out);
}

// round 9
// speedup vs baseline: 1.2913x; 1.0222x over previous
#include <cuda_runtime.h>
#include <cuda_bf16.h>
#include <math.h>

// ---------------------------------------------------------------------------
#define BB 512
#define VV 6890
#define NJ 24
#define NBETA 10
#define NP 207
#define NJO 19
#define VC (VV*3)              // 20670
#define VCP 20736              // padded cols (216*96, mult of 4)
#define KTOT 217
#define KPAD 224               // 7*32
#define JNT_OFF  (BB*VC)
#define ROT_OFF  (JNT_OFF + BB*NJO*3)

typedef unsigned long long u64;

__device__ __forceinline__ u64 ffma2(u64 a, u64 b, u64 c) {
    u64 d;
    asm("fma.rn.f32x2 %0, %1, %2, %3;" : "=l"(d) : "l"(a), "l"(b), "l"(c));
    return d;
}
__device__ __forceinline__ u64 pack2(float lo, float hi) {
    u64 d;
    asm("mov.b64 %0, {%1, %2};" : "=l"(d) : "f"(lo), "f"(hi));
    return d;
}
__device__ __forceinline__ float2 unpack2(u64 v) {
    float2 f;
    asm("mov.b64 {%0, %1}, %2;" : "=f"(f.x), "=f"(f.y) : "l"(v));
    return f;
}
__device__ __forceinline__ void cp_async16(unsigned saddr, const void* gaddr) {
    asm volatile("cp.async.ca.shared.global [%0], [%1], 16;"
                 :: "r"(saddr), "l"(gaddr));
}
__device__ __forceinline__ void cp_commit() {
    asm volatile("cp.async.commit_group;");
}
template<int N>
__device__ __forceinline__ void cp_wait() {
    asm volatile("cp.async.wait_group %0;" :: "n"(N));
}
__device__ __forceinline__ float tf32r(float x) {
    unsigned u;
    asm("cvt.rna.tf32.f32 %0, %1;" : "=r"(u) : "f"(x));
    return __uint_as_float(u);
}
__device__ __forceinline__ unsigned tf32u(float x) {
    unsigned u;
    asm("cvt.rna.tf32.f32 %0, %1;" : "=r"(u) : "f"(x));
    return u;
}
__device__ __forceinline__ void mma_tf32(float* c, const unsigned* a, unsigned b0, unsigned b1) {
    asm("mma.sync.aligned.m16n8k8.row.col.f32.tf32.tf32.f32 "
        "{%0,%1,%2,%3},{%4,%5,%6,%7},{%8,%9},{%0,%1,%2,%3};"
        : "+f"(c[0]), "+f"(c[1]), "+f"(c[2]), "+f"(c[3])
        : "r"(a[0]), "r"(a[1]), "r"(a[2]), "r"(a[3]), "r"(b0), "r"(b1));
}

// ---------------------------------------------------------------------------
__device__ float    g_pfT[KPAD * BB];     // pose-feature+beta (tf32-rounded), [k][b]
__device__ unsigned g_pd[(size_t)KPAD * VCP];  // tf32 bits of [posedirs;shapes], padded
__device__ float    g_A[BB * NJ * 12];    // A' 3x4 per (b,j)
__device__ float    g_jmp[NJ * 8 * 33];
__device__ float    g_jm[NJ * 33];
__device__ float    g_jpart[BB * 14 * 57];

// ---------------------------------------------------------------------------
// Kernel R: pre-round [posedirs;shapes] -> g_pd (tf32 bits, padded, zero-filled)
// ---------------------------------------------------------------------------
__global__ void __launch_bounds__(256) k_round(const float* __restrict__ pd,
                                               const float* __restrict__ sh)
{
    int k  = blockIdx.y;
    int c4 = (blockIdx.x * 256 + threadIdx.x) * 4;
    if (c4 >= VCP) return;
    uint4 o;
    #pragma unroll
    for (int e = 0; e < 4; ++e) {
        int c = c4 + e;
        float f = 0.f;
        if (c < VC) {
            if (k < NP)        f = pd[(size_t)k*VC + c];
            else if (k < KTOT) f = sh[(size_t)(k-NP)*VC + c];
        }
        (&o.x)[e] = tf32u(f);
    }
    *reinterpret_cast<uint4*>(&g_pd[(size_t)k*VCP + c4]) = o;
}

// ---------------------------------------------------------------------------
// Kernel 0: batch-independent precompute for rest joints
// ---------------------------------------------------------------------------
__global__ void __launch_bounds__(128) k_jm(const float* __restrict__ vt,
                                            const float* __restrict__ shp,
                                            const float* __restrict__ sr)
{
    int j = blockIdx.x, part = blockIdx.y;
    int vs = part * 862;
    int ve = vs + 862; if (ve > VV) ve = VV;

    float acc[33];
    #pragma unroll
    for (int i = 0; i < 33; ++i) acc[i] = 0.f;

    for (int v = vs + threadIdx.x; v < ve; v += 128) {
        float w = sr[v * NJ + j];
        acc[0] += vt[v*3+0] * w;
        acc[1] += vt[v*3+1] * w;
        acc[2] += vt[v*3+2] * w;
        #pragma unroll
        for (int k = 0; k < NBETA; ++k) {
            const float* s = shp + k * VC + v * 3;
            acc[3+k*3+0] += s[0] * w;
            acc[3+k*3+1] += s[1] * w;
            acc[3+k*3+2] += s[2] * w;
        }
    }
    #pragma unroll
    for (int m = 16; m > 0; m >>= 1)
        #pragma unroll
        for (int i = 0; i < 33; ++i)
            acc[i] += __shfl_xor_sync(0xffffffffu, acc[i], m);

    __shared__ float s[4][33];
    int wid = threadIdx.x >> 5, lane = threadIdx.x & 31;
    if (lane == 0)
        #pragma unroll
        for (int i = 0; i < 33; ++i) s[wid][i] = acc[i];
    __syncthreads();
    if (threadIdx.x < 33) {
        float t = s[0][threadIdx.x] + s[1][threadIdx.x] + s[2][threadIdx.x] + s[3][threadIdx.x];
        g_jmp[(j*8 + part)*33 + threadIdx.x] = t;
    }
}

__global__ void k_jmred()
{
    int i = blockIdx.x * blockDim.x + threadIdx.x;
    if (i < NJ * 33) {
        int jj = i / 33, r = i % 33;
        float t = 0.f;
        #pragma unroll
        for (int p = 0; p < 8; ++p) t += g_jmp[(jj*8 + p)*33 + r];
        g_jm[i] = t;
    }
}

// ---------------------------------------------------------------------------
// Kernel 1: fused Rodrigues + kinematic chain. 32 batches per block.
// ---------------------------------------------------------------------------
__global__ void __launch_bounds__(96) k_rotchain(const float* __restrict__ inp,
                                                 float* __restrict__ out)
{
    const int PAR[NJ] = {0,0,0,0,1,2,3,4,5,6,7,8,9,9,9,12,13,14,16,17,18,19,20,21};
    __shared__ float s_jm[NJ * 33];
    __shared__ float sJ[32][NJ*3];
    __shared__ float sR[32][NJ*9];

    const int tid = threadIdx.x;
    const int b0 = blockIdx.x * 32;

    for (int i = tid; i < NJ*33; i += 96) s_jm[i] = g_jm[i];

    for (int i = tid; i < 32*NJ; i += 96) {
        int bl = i / NJ, j = i % NJ;
        int b = b0 + bl;
        float rx = inp[b*82 + j*3 + 0];
        float ry = inp[b*82 + j*3 + 1];
        float rz = inp[b*82 + j*3 + 2];
        float ax = rx + 1e-8f, ay = ry + 1e-8f, az = rz + 1e-8f;
        float ang = sqrtf(ax*ax + ay*ay + az*az);
        float inv = 1.0f / ang;
        float nx = rx * inv, ny = ry * inv, nz = rz * inv;
        float c = cosf(ang), sn = sinf(ang), ic = 1.0f - c;
        float R[9];
        R[0] = c + ic*nx*nx;     R[1] = ic*nx*ny - sn*nz; R[2] = ic*nx*nz + sn*ny;
        R[3] = ic*ny*nx + sn*nz; R[4] = c + ic*ny*ny;     R[5] = ic*ny*nz - sn*nx;
        R[6] = ic*nz*nx - sn*ny; R[7] = ic*nz*ny + sn*nx; R[8] = c + ic*nz*nz;

        float* ro = out + ROT_OFF + (size_t)b*(NJ*9) + j*9;
        #pragma unroll
        for (int e = 0; e < 9; ++e) { ro[e] = R[e]; sR[bl][j*9+e] = R[e]; }

        if (j > 0) {
            int base = (j-1) * 9;
            #pragma unroll
            for (int e = 0; e < 9; ++e)
                g_pfT[(base + e) * BB + b] = tf32r(R[e] - ((e==0||e==4||e==8) ? 1.0f : 0.0f));
        }
    }
    __syncthreads();

    for (int i = tid; i < 32*NJ*3; i += 96) {
        int bl = i / 72, rem = i % 72;
        int j = rem / 3, c = rem % 3;
        int b = b0 + bl;
        float t = s_jm[j*33 + c];
        #pragma unroll
        for (int k = 0; k < NBETA; ++k)
            t = fmaf(inp[b*82 + 72 + k], s_jm[j*33 + 3 + k*3 + c], t);
        sJ[bl][j*3 + c] = t;
    }
    __syncthreads();

    const int bl = tid / 3;
    const int r  = tid % 3;
    const int b  = b0 + bl;
    const float* Rb = sR[bl];

    float row[NJ][3];
    float tw[NJ];
    row[0][0] = Rb[r*3+0]; row[0][1] = Rb[r*3+1]; row[0][2] = Rb[r*3+2];
    tw[0] = sJ[bl][r];

    #pragma unroll
    for (int j = 1; j < NJ; ++j) {
        const int p = PAR[j];
        float t0 = sJ[bl][j*3+0] - sJ[bl][p*3+0];
        float t1 = sJ[bl][j*3+1] - sJ[bl][p*3+1];
        float t2 = sJ[bl][j*3+2] - sJ[bl][p*3+2];
        float p0 = row[p][0], p1 = row[p][1], p2 = row[p][2];
        row[j][0] = p0*Rb[j*9+0] + p1*Rb[j*9+3] + p2*Rb[j*9+6];
        row[j][1] = p0*Rb[j*9+1] + p1*Rb[j*9+4] + p2*Rb[j*9+7];
        row[j][2] = p0*Rb[j*9+2] + p1*Rb[j*9+5] + p2*Rb[j*9+8];
        tw[j] = p0*t0 + p1*t1 + p2*t2 + tw[p];
    }

    float* Ao = g_A + (size_t)b * (NJ*12);
    #pragma unroll
    for (int j = 0; j < NJ; ++j) {
        float tp = tw[j] - (row[j][0]*sJ[bl][j*3+0] + row[j][1]*sJ[bl][j*3+1] + row[j][2]*sJ[bl][j*3+2]);
        float4 st = make_float4(row[j][0], row[j][1], row[j][2], tp);
        *reinterpret_cast<float4*>(&Ao[j*12 + r*4]) = st;
    }

    if (r == 0) {
        #pragma unroll
        for (int k = 0; k < NBETA; ++k) g_pfT[(NP + k)*BB + b] = tf32r(inp[b*82 + 72 + k]);
        #pragma unroll
        for (int k = KTOT; k < KPAD; ++k) g_pfT[k*BB + b] = 0.0f;
    }
}

// ---------------------------------------------------------------------------
// Kernel 2: blendshape GEMM (mma.sync tf32) + LBS skinning epilogue.
// Tile: 128 batches x 96 cols, 256 threads (8 warps, each M=16 x N=96).
// d: pre-rounded tf32 bits from g_pd via cp.async.16, double-buffered [32][104].
// pf: single smem buffer [32][136], next kt register-staged (LDG->regs->STS).
// smem floats: s_d 2x3328 @0 | s_pf 4352 @6656 | s_w 800 @11008 | s_vt 96 @11808
// epilogue alias: s_A @0 (4608), s_vp @4608 (1536). Total 11904 f = 47.6 KB.
// ---------------------------------------------------------------------------
__global__ void __launch_bounds__(256, 2) k_main(const float* __restrict__ lbs,
                                                 const float* __restrict__ vtempl,
                                                 float* __restrict__ out)
{
    __shared__ __align__(16) float smem[11904];
    float* s_d  = smem;            // 2 x 3328
    float* s_pf = smem + 6656;     // 32 x 136
    float* s_A  = smem;            // epilogue alias
    float* s_vp = smem + 4608;     // epilogue alias
    float* s_w  = smem + 11008;    // [32][25]
    float* s_vt = smem + 11808;    // [96]

    const int b0   = blockIdx.y * 128;
    const int col0 = blockIdx.x * 96;
    const int v0   = blockIdx.x * 32;
    const int tid  = threadIdx.x;
    const int lane = tid & 31;
    const int warp = tid >> 5;        // warp_m: 16 batches each
    const int g  = lane >> 2;         // 0..7
    const int tg = lane & 3;          // 0..3

    const unsigned sd_base = (unsigned)__cvta_generic_to_shared(s_d);

    auto load_d = [&](int kt, int buf) {
        #pragma unroll
        for (int it = 0; it < 3; ++it) {
            int i = tid + it*256;          // 0..767
            int k = i / 24, q = i % 24;
            cp_async16(sd_base + (unsigned)(buf*3328 + k*104 + q*4)*4u,
                       g_pd + (size_t)(kt*32 + k)*VCP + col0 + q*4);
        }
        cp_commit();
    };

    // initial pf tile (kt=0) straight to smem
    {
        #pragma unroll
        for (int r = 0; r < 4; ++r) {
            int c = tid + r*256;           // 0..1023
            int k = c >> 5, q = c & 31;
            float4 v = *reinterpret_cast<const float4*>(&g_pfT[k*BB + b0 + q*4]);
            *reinterpret_cast<float4*>(&s_pf[k*136 + q*4]) = v;
        }
    }
    load_d(0, 0);

    float c[12][4];
    #pragma unroll
    for (int i = 0; i < 12; ++i)
        #pragma unroll
        for (int e = 0; e < 4; ++e) c[i][e] = 0.f;

    for (int kt = 0; kt < 7; ++kt) {
        const int buf = kt & 1;
        // prefetch next pf tile into registers, issue next d tile cp.async
        uint4 rpf[2];
        int rk[2], rq[2];
        if (kt < 6) {
            load_d(kt+1, buf ^ 1);
            #pragma unroll
            for (int r = 0; r < 2; ++r) {
                int cc = tid + r*256 + ((tid >= 128) ? 0 : 0);   // 0..511
                // 1024 chunks over 256 threads -> 4, but stage 2 now + 2 in 2nd half
                (void)cc;
            }
            #pragma unroll
            for (int r = 0; r < 2; ++r) {
                int cc = tid*2 + r + 0;    // not used
                (void)cc;
            }
            #pragma unroll
            for (int r = 0; r < 2; ++r) {
                int cc = tid + r*256;      // first 512 of 1024 chunks
                (void)cc;
            }
            // each thread stages 4 float4? too many regs; stage 2x uint4 covering
            // 512 chunks; remaining 512 loaded after compute directly.
            #pragma unroll
            for (int r = 0; r < 2; ++r) {
                int cc = tid + r*256;
                rk[r] = cc >> 5; rq[r] = cc & 31;
                rpf[r] = *reinterpret_cast<const uint4*>(
                    &g_pfT[((kt+1)*32 + rk[r])*BB + b0 + rq[r]*4]);
            }
        }
        if (kt < 6) cp_wait<1>(); else cp_wait<0>();
        __syncthreads();

        const float*    pa = s_pf + tg*136 + warp*16 + g;
        const unsigned* pb = reinterpret_cast<const unsigned*>(s_d + buf*3328) + tg*104 + g;

        #pragma unroll
        for (int ks = 0; ks < 4; ++ks) {
            const float*    pak = pa + ks*1088;   // ks*8*136
            const unsigned* pbk = pb + ks*832;    // ks*8*104
            unsigned a[4];
            a[0] = __float_as_uint(pak[0]);
            a[1] = __float_as_uint(pak[8]);
            a[2] = __float_as_uint(pak[544]);     // +4*136
            a[3] = __float_as_uint(pak[552]);
            #pragma unroll
            for (int nt = 0; nt < 12; ++nt) {
                unsigned bb0 = pbk[nt*8];
                unsigned bb1 = pbk[nt*8 + 416];   // +4*104
                mma_tf32(c[nt], a, bb0, bb1);
            }
        }
        __syncthreads();

        if (kt < 6) {
            // store staged pf regs + load the remaining half directly
            #pragma unroll
            for (int r = 0; r < 2; ++r)
                *reinterpret_cast<uint4*>(&s_pf[rk[r]*136 + rq[r]*4]) = rpf[r];
            #pragma unroll
            for (int r = 2; r < 4; ++r) {
                int cc = tid + r*256;             // 512..1023
                int k = cc >> 5, q = cc & 31;
                float4 v = *reinterpret_cast<const float4*>(
                    &g_pfT[((kt+1)*32 + k)*BB + b0 + q*4]);
                *reinterpret_cast<float4*>(&s_pf[k*136 + q*4]) = v;
            }
        }
    }

    // ---- epilogue: LBS skinning ----
    for (int i = tid; i < 768; i += 256) {
        int vl = i / 24, j = i % 24;
        int v = v0 + vl;
        s_w[vl*25 + j] = (v < VV) ? lbs[(size_t)v*NJ + j] : 0.f;
    }
    if (tid < 96) {
        int cg = col0 + tid;
        s_vt[tid] = (cg < VC) ? vtempl[cg] : 0.f;
    }

    const u64 z2 = pack2(0.f, 0.f);
    const int tv = tid & 15;
    const int tb = tid >> 4;
    const int vg0 = v0 + tv*2;
    const int vg1 = vg0 + 1;

    #pragma unroll
    for (int pass = 0; pass < 8; ++pass) {
        __syncthreads();
        if (warp == pass) {
            #pragma unroll
            for (int nt = 0; nt < 12; ++nt) {
                int colL = nt*8 + tg*2;
                float vt0 = s_vt[colL], vt1 = s_vt[colL+1];
                s_vp[g*96 + colL]        = c[nt][0] + vt0;
                s_vp[g*96 + colL + 1]    = c[nt][1] + vt1;
                s_vp[(g+8)*96 + colL]    = c[nt][2] + vt0;
                s_vp[(g+8)*96 + colL+1]  = c[nt][3] + vt1;
            }
        }
        {
            const float4* gA4 = reinterpret_cast<const float4*>(g_A + (size_t)(b0 + pass*16)*288);
            #pragma unroll
            for (int i = 0; i < 5; ++i) {
                int idx = tid + i*256;
                if (idx < 1152) reinterpret_cast<float4*>(s_A)[idx] = gA4[idx];
            }
        }
        __syncthreads();

        const int b = b0 + pass*16 + tb;
        const ulonglong2* Ar2 = reinterpret_cast<const ulonglong2*>(s_A + tb*288);
        u64 T0[6], T1[6];
        #pragma unroll
        for (int i = 0; i < 6; ++i) { T0[i] = z2; T1[i] = z2; }
        #pragma unroll
        for (int j = 0; j < NJ; ++j) {
            ulonglong2 A01 = Ar2[j*3 + 0];
            ulonglong2 A23 = Ar2[j*3 + 1];
            ulonglong2 A45 = Ar2[j*3 + 2];
            float w0 = s_w[(tv*2 + 0)*25 + j];
            float w1 = s_w[(tv*2 + 1)*25 + j];
            u64 w0d = pack2(w0, w0);
            u64 w1d = pack2(w1, w1);
            T0[0] = ffma2(w0d, A01.x, T0[0]); T0[1] = ffma2(w0d, A01.y, T0[1]);
            T0[2] = ffma2(w0d, A23.x, T0[2]); T0[3] = ffma2(w0d, A23.y, T0[3]);
            T0[4] = ffma2(w0d, A45.x, T0[4]); T0[5] = ffma2(w0d, A45.y, T0[5]);
            T1[0] = ffma2(w1d, A01.x, T1[0]); T1[1] = ffma2(w1d, A01.y, T1[1]);
            T1[2] = ffma2(w1d, A23.x, T1[2]); T1[3] = ffma2(w1d, A23.y, T1[3]);
            T1[4] = ffma2(w1d, A45.x, T1[4]); T1[5] = ffma2(w1d, A45.y, T1[5]);
        }
        if (vg0 < VV) {
            float x = s_vp[tb*96 + tv*6 + 0];
            float y = s_vp[tb*96 + tv*6 + 1];
            float z = s_vp[tb*96 + tv*6 + 2];
            float2 r0 = unpack2(T0[0]), r1 = unpack2(T0[1]);
            float2 r2 = unpack2(T0[2]), r3 = unpack2(T0[3]);
            float2 r4 = unpack2(T0[4]), r5 = unpack2(T0[5]);
            float* o = out + (size_t)b*VC + vg0*3;
            o[0] = r0.x*x + r0.y*y + r1.x*z + r1.y;
            o[1] = r2.x*x + r2.y*y + r3.x*z + r3.y;
            o[2] = r4.x*x + r4.y*y + r5.x*z + r5.y;
        }
        if (vg1 < VV) {
            float x = s_vp[tb*96 + tv*6 + 3];
            float y = s_vp[tb*96 + tv*6 + 4];
            float z = s_vp[tb*96 + tv*6 + 5];
            float2 r0 = unpack2(T1[0]), r1 = unpack2(T1[1]);
            float2 r2 = unpack2(T1[2]), r3 = unpack2(T1[3]);
            float2 r4 = unpack2(T1[4]), r5 = unpack2(T1[5]);
            float* o = out + (size_t)b*VC + vg1*3;
            o[0] = r0.x*x + r0.y*y + r1.x*z + r1.y;
            o[1] = r2.x*x + r2.y*y + r3.x*z + r3.y;
            o[2] = r4.x*x + r4.y*y + r5.x*z + r5.y;
        }
    }
}

// ---------------------------------------------------------------------------
// Kernel 3: joints = vertices @ joint_regressor (deterministic 2-stage)
// ---------------------------------------------------------------------------
__global__ void __launch_bounds__(256) k_jnt_part(const float* __restrict__ outv,
                                                  const float* __restrict__ jreg)
{
    __shared__ float s_jr[512 * NJO];
    const int chunk = blockIdx.x;
    const int v0 = chunk * 512;
    for (int i = threadIdx.x; i < 512*NJO; i += 256) {
        int v = v0 + i / NJO;
        s_jr[i] = (v < VV) ? jreg[v*NJO + (i % NJO)] : 0.f;
    }
    __syncthreads();

    const int bl = threadIdx.x >> 5, lane = threadIdx.x & 31;
    const int b = blockIdx.y * 8 + bl;

    float acc[57];
    #pragma unroll
    for (int i = 0; i < 57; ++i) acc[i] = 0.f;

    #pragma unroll 4
    for (int i = 0; i < 16; ++i) {
        int vl = lane + i*32;
        int vg = v0 + vl;
        if (vg < VV) {
            const float* p = outv + (size_t)b*VC + vg*3;
            float x = p[0], y = p[1], z = p[2];
            #pragma unroll
            for (int j = 0; j < NJO; ++j) {
                float r = s_jr[vl*NJO + j];
                acc[j*3+0] = fmaf(r, x, acc[j*3+0]);
                acc[j*3+1] = fmaf(r, y, acc[j*3+1]);
                acc[j*3+2] = fmaf(r, z, acc[j*3+2]);
            }
        }
    }
    #pragma unroll
    for (int m = 16; m > 0; m >>= 1)
        #pragma unroll
        for (int i = 0; i < 57; ++i)
            acc[i] += __shfl_xor_sync(0xffffffffu, acc[i], m);

    if (lane == 0) {
        float* dst = g_jpart + (size_t)(b*14 + chunk)*57;
        #pragma unroll
        for (int i = 0; i < 57; ++i) dst[i] = acc[i];
    }
}

__global__ void k_jnt_red(float* __restrict__ out)
{
    int i = blockIdx.x * blockDim.x + threadIdx.x;
    if (i < BB * 57) {
        int b = i / 57, r = i % 57;
        float t = 0.f;
        #pragma unroll
        for (int p = 0; p < 14; ++p) t += g_jpart[(size_t)(b*14 + p)*57 + r];
        out[JNT_OFF + i] = t;
    }
}

// ---------------------------------------------------------------------------
extern "C" void kernel_launch(void* const* d_in, const int* in_sizes, int n_in,
                              void* d_out, int out_size)
{
    const float* inputs   = (const float*)d_in[0];
    const float* v_templ  = (const float*)d_in[1];
    const float* shapes   = (const float*)d_in[2];
    const float* posedirs = (const float*)d_in[3];
    const float* smpl_reg = (const float*)d_in[4];
    const float* lbs_w    = (const float*)d_in[5];
    const float* joint_rg = (const float*)d_in[6];
    float* out = (float*)d_out;

    k_round<<<dim3(21, KPAD), 256>>>(posedirs, shapes);

    k_jm<<<dim3(NJ, 8), 128>>>(v_templ, shapes, smpl_reg);
    k_jmred<<<4, 256>>>();

    k_rotchain<<<16, 96>>>(inputs, out);

    k_main<<<dim3(216, 4), 256>>>(lbs_w, v_templ, out);

    k_jnt_part<<<dim3(14, 64), 256>>>(out, joint_rg);
    k_jnt_red<<<(BB*57 + 255)/256, 256>>>(out);
}